// round 1
// baseline (speedup 1.0000x reference)
#include <cuda_runtime.h>

#define T_TOTAL 65536
#define HDIM    512
#define NE      4
#define NBLK    256
#define SEQLEN  8192
#define NBATCH  8
#define ALPHA   0.1f

// Per-block partial sums for the aux loss (deterministic, no atomics).
__device__ float g_blk_sum[NBLK][NE];  // sum of softmax scores over block's tokens
__device__ float g_blk_cnt[NBLK][NE];  // top-2 selection counts (as float)

__global__ void __launch_bounds__(256, 2)
moe_gate_kernel(const float* __restrict__ x, const float* __restrict__ w,
                float* __restrict__ out)
{
    const int lane = threadIdx.x & 31;
    const int wid  = threadIdx.x >> 5;

    // Load gate weights into registers: lane l owns h = i*128 + 4l, i=0..3.
    float4 wr[NE][4];
#pragma unroll
    for (int e = 0; e < NE; e++)
#pragma unroll
        for (int i = 0; i < 4; i++)
            wr[e][i] = *reinterpret_cast<const float4*>(w + e * HDIM + i * 128 + lane * 4);

    float lsum[NE] = {0.f, 0.f, 0.f, 0.f};
    float lcnt[NE] = {0.f, 0.f, 0.f, 0.f};

    const int t0 = blockIdx.x * 256 + wid * 32;   // 32 contiguous tokens per warp
    float* __restrict__ out_idx = out;
    float* __restrict__ out_w   = out + 2 * T_TOTAL;

#pragma unroll 2
    for (int tt = 0; tt < 32; tt++) {
        const int t = t0 + tt;
        const float* xb = x + (size_t)t * HDIM;

        float4 xv[4];
#pragma unroll
        for (int i = 0; i < 4; i++)
            xv[i] = *reinterpret_cast<const float4*>(xb + i * 128 + lane * 4);

        float acc[NE];
#pragma unroll
        for (int e = 0; e < NE; e++) {
            float a = 0.f;
#pragma unroll
            for (int i = 0; i < 4; i++) {
                a = fmaf(xv[i].x, wr[e][i].x, a);
                a = fmaf(xv[i].y, wr[e][i].y, a);
                a = fmaf(xv[i].z, wr[e][i].z, a);
                a = fmaf(xv[i].w, wr[e][i].w, a);
            }
            acc[e] = a;
        }

        // Full butterfly reduction: every lane ends with the 4 logits.
#pragma unroll
        for (int off = 16; off >= 1; off >>= 1)
#pragma unroll
            for (int e = 0; e < NE; e++)
                acc[e] += __shfl_xor_sync(0xffffffffu, acc[e], off);

        // Softmax over 4 experts.
        float m = fmaxf(fmaxf(acc[0], acc[1]), fmaxf(acc[2], acc[3]));
        float s[NE];
        float ssum = 0.f;
#pragma unroll
        for (int e = 0; e < NE; e++) { s[e] = __expf(acc[e] - m); ssum += s[e]; }
        float inv = 1.0f / ssum;
#pragma unroll
        for (int e = 0; e < NE; e++) s[e] *= inv;

        // Top-2 (ties -> lowest index, matching lax.top_k).
        int i1 = 0; float v1 = s[0];
#pragma unroll
        for (int e = 1; e < NE; e++) if (s[e] > v1) { v1 = s[e]; i1 = e; }
        int i2 = -1; float v2 = -1.f;
#pragma unroll
        for (int e = 0; e < NE; e++) if (e != i1 && s[e] > v2) { v2 = s[e]; i2 = e; }

        float d  = v1 + v2 + 1e-20f;
        float nw1 = v1 / d, nw2 = v2 / d;

        if (lane == 0) {
            out_idx[2 * t]     = (float)i1;
            out_idx[2 * t + 1] = (float)i2;
            out_w[2 * t]       = nw1;
            out_w[2 * t + 1]   = nw2;
#pragma unroll
            for (int e = 0; e < NE; e++) lsum[e] += s[e];
            lcnt[i1] += 1.f;
            lcnt[i2] += 1.f;
        }
    }

    // Block-level deterministic reduction of aux-loss partials.
    __shared__ float sSum[8][NE];
    __shared__ float sCnt[8][NE];
    if (lane == 0) {
#pragma unroll
        for (int e = 0; e < NE; e++) { sSum[wid][e] = lsum[e]; sCnt[wid][e] = lcnt[e]; }
    }
    __syncthreads();
    if (threadIdx.x < NE) {
        int e = threadIdx.x;
        float a = 0.f, c = 0.f;
#pragma unroll
        for (int wg = 0; wg < 8; wg++) { a += sSum[wg][e]; c += sCnt[wg][e]; }
        g_blk_sum[blockIdx.x][e] = a;
        g_blk_cnt[blockIdx.x][e] = c;
    }
}

// One warp: 32 lanes = (batch, expert) pairs; fixed-order reduction -> deterministic.
__global__ void moe_gate_finalize(float* __restrict__ out)
{
    const int lane = threadIdx.x;  // 0..31
    const int b = lane >> 2;
    const int e = lane & 3;
    float s = 0.f, c = 0.f;
    const int blk0 = b * (NBLK / NBATCH);  // 32 blocks per batch
    for (int i = 0; i < NBLK / NBATCH; i++) {
        s += g_blk_sum[blk0 + i][e];
        c += g_blk_cnt[blk0 + i][e];
    }
    // ce_norm[b][e] * mean_score[b][e]
    float term = (c / ((float)SEQLEN * 2.0f / (float)NE)) * (s / (float)SEQLEN);
#pragma unroll
    for (int off = 16; off >= 1; off >>= 1)
        term += __shfl_xor_sync(0xffffffffu, term, off);
    if (lane == 0)
        out[4 * T_TOTAL] = term / (float)NBATCH * ALPHA;
}

extern "C" void kernel_launch(void* const* d_in, const int* in_sizes, int n_in,
                              void* d_out, int out_size)
{
    const float* x = (const float*)d_in[0];   // hidden_states [8, 8192, 512]
    const float* w = (const float*)d_in[1];   // weight [4, 512]
    float* out = (float*)d_out;               // [idx(2T), weight(2T), loss(1)]

    moe_gate_kernel<<<NBLK, 256>>>(x, w, out);
    moe_gate_finalize<<<1, 32>>>(out);
}

// round 7
// speedup vs baseline: 1.0722x; 1.0722x over previous
#include <cuda_runtime.h>

#define T_TOTAL 65536
#define HDIM    512
#define NE      4
#define NBLK    512        // 128 tokens per block, 16 per warp
#define SEQLEN  8192
#define NBATCH  8
#define ALPHA   0.1f
#define TOK_PER_WARP 16

// Per-block partial sums for the aux loss (deterministic, no atomics on floats).
__device__ float g_blk_sum[NBLK][NE];
__device__ float g_blk_cnt[NBLK][NE];
__device__ unsigned int g_ticket;   // zero-initialized; reset by last block each launch

__global__ void __launch_bounds__(256, 2)
moe_gate_kernel(const float* __restrict__ x, const float* __restrict__ w,
                float* __restrict__ out)
{
    const int lane = threadIdx.x & 31;
    const int wid  = threadIdx.x >> 5;

    // Gate weights in registers: lane l owns h = i*128 + 4l, i=0..3.
    float4 wr[NE][4];
#pragma unroll
    for (int e = 0; e < NE; e++)
#pragma unroll
        for (int i = 0; i < 4; i++)
            wr[e][i] = *reinterpret_cast<const float4*>(w + e * HDIM + i * 128 + lane * 4);

    float lsum[NE] = {0.f, 0.f, 0.f, 0.f};
    float lcnt[NE] = {0.f, 0.f, 0.f, 0.f};

    const int t0 = blockIdx.x * (8 * TOK_PER_WARP) + wid * TOK_PER_WARP;
    float* __restrict__ out_idx = out;
    float* __restrict__ out_w   = out + 2 * T_TOTAL;

    // 2-deep prefetch buffers -> up to 8 LDG.128 outstanding per warp.
    float4 xv[2][4];
    {
        const float* xb0 = x + (size_t)t0 * HDIM;
        const float* xb1 = x + (size_t)(t0 + 1) * HDIM;
#pragma unroll
        for (int i = 0; i < 4; i++)
            xv[0][i] = *reinterpret_cast<const float4*>(xb0 + i * 128 + lane * 4);
#pragma unroll
        for (int i = 0; i < 4; i++)
            xv[1][i] = *reinterpret_cast<const float4*>(xb1 + i * 128 + lane * 4);
    }

#pragma unroll 2
    for (int tt = 0; tt < TOK_PER_WARP; tt++) {
        const int cur = tt & 1;
        const int t = t0 + tt;

        float acc[NE];
#pragma unroll
        for (int e = 0; e < NE; e++) {
            float a = 0.f;
#pragma unroll
            for (int i = 0; i < 4; i++) {
                a = fmaf(xv[cur][i].x, wr[e][i].x, a);
                a = fmaf(xv[cur][i].y, wr[e][i].y, a);
                a = fmaf(xv[cur][i].z, wr[e][i].z, a);
                a = fmaf(xv[cur][i].w, wr[e][i].w, a);
            }
            acc[e] = a;
        }

        // Prefetch token tt+2 into the buffer we just consumed.
        if (tt + 2 < TOK_PER_WARP) {
            const float* xb = x + (size_t)(t + 2) * HDIM;
#pragma unroll
            for (int i = 0; i < 4; i++)
                xv[cur][i] = *reinterpret_cast<const float4*>(xb + i * 128 + lane * 4);
        }

        // Butterfly reduction: every lane ends with the 4 logits.
#pragma unroll
        for (int off = 16; off >= 1; off >>= 1)
#pragma unroll
            for (int e = 0; e < NE; e++)
                acc[e] += __shfl_xor_sync(0xffffffffu, acc[e], off);

        // Softmax over 4 experts.
        float m = fmaxf(fmaxf(acc[0], acc[1]), fmaxf(acc[2], acc[3]));
        float s[NE];
        float ssum = 0.f;
#pragma unroll
        for (int e = 0; e < NE; e++) { s[e] = __expf(acc[e] - m); ssum += s[e]; }
        float inv = 1.0f / ssum;
#pragma unroll
        for (int e = 0; e < NE; e++) s[e] *= inv;

        // Top-2 (ties -> lowest index, matching lax.top_k).
        int i1 = 0; float v1 = s[0];
#pragma unroll
        for (int e = 1; e < NE; e++) if (s[e] > v1) { v1 = s[e]; i1 = e; }
        int i2 = -1; float v2 = -1.f;
#pragma unroll
        for (int e = 0; e < NE; e++) if (e != i1 && s[e] > v2) { v2 = s[e]; i2 = e; }

        float d   = v1 + v2 + 1e-20f;
        float nw1 = v1 / d, nw2 = v2 / d;

        if (lane == 0) {
            *reinterpret_cast<float2*>(out_idx + 2 * t) = make_float2((float)i1, (float)i2);
            *reinterpret_cast<float2*>(out_w   + 2 * t) = make_float2(nw1, nw2);
#pragma unroll
            for (int e = 0; e < NE; e++) lsum[e] += s[e];
            lcnt[i1] += 1.f;
            lcnt[i2] += 1.f;
        }
    }

    // Block-level deterministic reduction of aux-loss partials.
    __shared__ float sSum[8][NE];
    __shared__ float sCnt[8][NE];
    __shared__ bool  sLast;
    if (lane == 0) {
#pragma unroll
        for (int e = 0; e < NE; e++) { sSum[wid][e] = lsum[e]; sCnt[wid][e] = lcnt[e]; }
    }
    __syncthreads();
    if (threadIdx.x < NE) {
        int e = threadIdx.x;
        float a = 0.f, c = 0.f;
#pragma unroll
        for (int wg = 0; wg < 8; wg++) { a += sSum[wg][e]; c += sCnt[wg][e]; }
        g_blk_sum[blockIdx.x][e] = a;
        g_blk_cnt[blockIdx.x][e] = c;
    }

    // Last-block finalize (fused second kernel).
    if (threadIdx.x == 0) {
        __threadfence();
        unsigned int v = atomicAdd(&g_ticket, 1u);
        sLast = (v == NBLK - 1);
    }
    __syncthreads();
    if (sLast) {
        if (threadIdx.x < 32) {
            const int b = threadIdx.x >> 2;      // batch
            const int e = threadIdx.x & 3;       // expert
            float s = 0.f, c = 0.f;
            const int blk0 = b * (NBLK / NBATCH);  // 64 blocks per batch, contiguous
#pragma unroll 8
            for (int i = 0; i < NBLK / NBATCH; i++) {
                s += g_blk_sum[blk0 + i][e];
                c += g_blk_cnt[blk0 + i][e];
            }
            float term = (c / ((float)SEQLEN * 2.0f / (float)NE)) * (s / (float)SEQLEN);
#pragma unroll
            for (int off = 16; off >= 1; off >>= 1)
                term += __shfl_xor_sync(0xffffffffu, term, off);
            if (threadIdx.x == 0) {
                out[4 * T_TOTAL] = term / (float)NBATCH * ALPHA;
                g_ticket = 0;   // reset for next graph replay
            }
        }
    }
}

extern "C" void kernel_launch(void* const* d_in, const int* in_sizes, int n_in,
                              void* d_out, int out_size)
{
    const float* x = (const float*)d_in[0];   // hidden_states [8, 8192, 512]
    const float* w = (const float*)d_in[1];   // weight [4, 512]
    float* out = (float*)d_out;               // [idx(2T), weight(2T), loss(1)]

    moe_gate_kernel<<<NBLK, 256>>>(x, w, out);
}

// round 17
// speedup vs baseline: 1.1447x; 1.0676x over previous
#include <cuda_runtime.h>

#define T_TOTAL 65536
#define HDIM    512
#define NE      4
#define NBLK    512        // 128 tokens per block, 16 per warp (4 iters x 4 tokens)
#define SEQLEN  8192
#define NBATCH  8
#define ALPHA   0.1f

// Per-block partial sums for the aux loss (deterministic; values are 2x true due
// to lane replication, corrected in the finalize).
__device__ float g_blk_sum[NBLK][NE];
__device__ float g_blk_cnt[NBLK][NE];
__device__ unsigned int g_ticket;   // zero-init; reset by last block each launch

__global__ void __launch_bounds__(256, 2)
moe_gate_kernel(const float* __restrict__ x, const float* __restrict__ w,
                float* __restrict__ out)
{
    __shared__ float4 w_s4[512];          // 4 experts x 512 floats (8 KB)
    __shared__ float sSum[8][NE];
    __shared__ float sCnt[8][NE];
    __shared__ bool  sLast;

    const int tid  = threadIdx.x;
    const int lane = tid & 31;
    const int wid  = tid >> 5;

    // Cooperative weight load into smem.
    const float4* w4 = reinterpret_cast<const float4*>(w);
    w_s4[tid]       = w4[tid];
    w_s4[tid + 256] = w4[tid + 256];
    __syncthreads();

    const int tbase = blockIdx.x * 128 + wid * 16;
    const int my_e  = lane & 3;               // expert this lane owns post-fold
    const int b0 = lane & 1, b1 = (lane >> 1) & 1, b2 = (lane >> 2) & 1, b3 = (lane >> 3) & 1;

    float ssum_l = 0.f, cnt_l = 0.f;
    float* __restrict__ out_idx = out;
    float* __restrict__ out_w   = out + 2 * T_TOTAL;

    // 4 tokens in flight: 16 LDG.128 issued together.
    float4 xv[4][4];
    {
        const float* xb = x + (size_t)tbase * HDIM;
#pragma unroll
        for (int t = 0; t < 4; t++)
#pragma unroll
            for (int i = 0; i < 4; i++)
                xv[t][i] = *reinterpret_cast<const float4*>(xb + t * HDIM + i * 128 + lane * 4);
    }

#pragma unroll
    for (int it = 0; it < 4; it++) {
        // ---- dot products: acc[token][expert], weights streamed from smem ----
        float acc[4][4];
#pragma unroll
        for (int t = 0; t < 4; t++)
#pragma unroll
            for (int e = 0; e < 4; e++) acc[t][e] = 0.f;

#pragma unroll
        for (int i = 0; i < 4; i++) {
#pragma unroll
            for (int e = 0; e < 4; e++) {
                float4 wv = w_s4[e * 128 + i * 32 + lane];
#pragma unroll
                for (int t = 0; t < 4; t++) {
                    acc[t][e] = fmaf(xv[t][i].x, wv.x, acc[t][e]);
                    acc[t][e] = fmaf(xv[t][i].y, wv.y, acc[t][e]);
                    acc[t][e] = fmaf(xv[t][i].z, wv.z, acc[t][e]);
                    acc[t][e] = fmaf(xv[t][i].w, wv.w, acc[t][e]);
                }
            }
        }

        // ---- prefetch next 4 tokens (overlaps with the fold/softmax chain) ----
        if (it < 3) {
            const float* xb = x + (size_t)(tbase + (it + 1) * 4) * HDIM;
#pragma unroll
            for (int t = 0; t < 4; t++)
#pragma unroll
                for (int i = 0; i < 4; i++)
                    xv[t][i] = *reinterpret_cast<const float4*>(xb + t * HDIM + i * 128 + lane * 4);
        }

        // ---- fold 16 (tok,exp) partials -> lane l owns (tok=l>>2&3, exp=l&3) ----
        float v[4][2];
#pragma unroll
        for (int t = 0; t < 4; t++)
#pragma unroll
            for (int p = 0; p < 2; p++) {
                float keep = b0 ? acc[t][2*p+1] : acc[t][2*p];
                float send = b0 ? acc[t][2*p]   : acc[t][2*p+1];
                v[t][p] = keep + __shfl_xor_sync(0xffffffffu, send, 1);
            }
        float u[4];
#pragma unroll
        for (int t = 0; t < 4; t++) {
            float keep = b1 ? v[t][1] : v[t][0];
            float send = b1 ? v[t][0] : v[t][1];
            u[t] = keep + __shfl_xor_sync(0xffffffffu, send, 2);
        }
        float r[2];
#pragma unroll
        for (int p = 0; p < 2; p++) {
            float keep = b2 ? u[2*p+1] : u[2*p];
            float send = b2 ? u[2*p]   : u[2*p+1];
            r[p] = keep + __shfl_xor_sync(0xffffffffu, send, 4);
        }
        float z;
        {
            float keep = b3 ? r[1] : r[0];
            float send = b3 ? r[0] : r[1];
            z = keep + __shfl_xor_sync(0xffffffffu, send, 8);
        }
        z += __shfl_xor_sync(0xffffffffu, z, 16);

        // ---- per-token softmax in each 4-lane group ----
        float m1 = fmaxf(z, __shfl_xor_sync(0xffffffffu, z, 1));
        float m  = fmaxf(m1, __shfl_xor_sync(0xffffffffu, m1, 2));
        float ex = __expf(z - m);
        float e1 = __shfl_xor_sync(0xffffffffu, ex, 1);   // expert my_e^1
        float e2 = __shfl_xor_sync(0xffffffffu, ex, 2);   // expert my_e^2
        float e3 = __shfl_xor_sync(0xffffffffu, ex, 3);   // expert my_e^3
        float denom = ex + e1 + e2 + e3;

        // ---- top-2 with index tie-break (order-independent across lanes) ----
        const int j1 = my_e ^ 1, j2 = my_e ^ 2, j3 = my_e ^ 3;
        bool pA = (ex > e1) || (ex == e1 && my_e < j1);
        float hAv = pA ? ex : e1;  int hAi = pA ? my_e : j1;
        float lAv = pA ? e1 : ex;  int lAi = pA ? j1 : my_e;
        bool pB = (e2 > e3) || (e2 == e3 && j2 < j3);
        float hBv = pB ? e2 : e3;  int hBi = pB ? j2 : j3;
        float lBv = pB ? e3 : e2;  int lBi = pB ? j3 : j2;
        bool pF = (hAv > hBv) || (hAv == hBv && hAi < hBi);
        float t1v = pF ? hAv : hBv;  int t1i = pF ? hAi : hBi;
        float c2v = pF ? hBv : hAv;  int c2i = pF ? hBi : hAi;   // losing finalist
        float o2v = pF ? lAv : lBv;  int o2i = pF ? lAi : lBi;   // winner-pair loser
        bool pS = (o2v > c2v) || (o2v == c2v && o2i < c2i);
        float t2v = pS ? o2v : c2v;  int t2i = pS ? o2i : c2i;

        float dd  = t1v + t2v;
        float nw1 = t1v / dd;
        float nw2 = t2v / dd;

        if ((lane & 3) == 0 && lane < 16) {
            int t = tbase + it * 4 + (lane >> 2);
            *reinterpret_cast<float2*>(out_idx + 2 * t) = make_float2((float)t1i, (float)t2i);
            *reinterpret_cast<float2*>(out_w   + 2 * t) = make_float2(nw1, nw2);
        }

        // ---- aux partials: own-expert only (no dynamic indexing); 2x replicated ----
        ssum_l += ex / denom;
        cnt_l  += (my_e == t1i ? 1.f : 0.f) + (my_e == t2i ? 1.f : 0.f);
    }

    // ---- warp fold of aux partials: lanes {e, e+4, ...} -> expert e totals ----
    ssum_l += __shfl_xor_sync(0xffffffffu, ssum_l, 4);
    ssum_l += __shfl_xor_sync(0xffffffffu, ssum_l, 8);
    ssum_l += __shfl_xor_sync(0xffffffffu, ssum_l, 16);
    cnt_l  += __shfl_xor_sync(0xffffffffu, cnt_l, 4);
    cnt_l  += __shfl_xor_sync(0xffffffffu, cnt_l, 8);
    cnt_l  += __shfl_xor_sync(0xffffffffu, cnt_l, 16);

    if (lane < NE) { sSum[wid][lane] = ssum_l; sCnt[wid][lane] = cnt_l; }
    __syncthreads();
    if (tid < NE) {
        float a = 0.f, c = 0.f;
#pragma unroll
        for (int wg = 0; wg < 8; wg++) { a += sSum[wg][tid]; c += sCnt[wg][tid]; }
        g_blk_sum[blockIdx.x][tid] = a;   // 2x true
        g_blk_cnt[blockIdx.x][tid] = c;   // 2x true
    }

    // ---- last-block finalize ----
    if (tid == 0) {
        __threadfence();
        unsigned int vt = atomicAdd(&g_ticket, 1u);
        sLast = (vt == NBLK - 1);
    }
    __syncthreads();
    if (sLast && tid < 32) {
        const int b = tid >> 2;               // batch
        const int e = tid & 3;                // expert
        float s = 0.f, c = 0.f;
        const int blk0 = b * (NBLK / NBATCH); // 64 blocks per batch, contiguous
#pragma unroll 8
        for (int i = 0; i < NBLK / NBATCH; i++) {
            s += g_blk_sum[blk0 + i][e];
            c += g_blk_cnt[blk0 + i][e];
        }
        s *= 0.5f;  c *= 0.5f;                // undo lane replication
        float term = (c / ((float)SEQLEN * 2.0f / (float)NE)) * (s / (float)SEQLEN);
#pragma unroll
        for (int off = 16; off >= 1; off >>= 1)
            term += __shfl_xor_sync(0xffffffffu, term, off);
        if (tid == 0) {
            out[4 * T_TOTAL] = term / (float)NBATCH * ALPHA;
            g_ticket = 0;                     // reset for next graph replay
        }
    }
}

extern "C" void kernel_launch(void* const* d_in, const int* in_sizes, int n_in,
                              void* d_out, int out_size)
{
    const float* x = (const float*)d_in[0];   // hidden_states [8, 8192, 512]
    const float* w = (const float*)d_in[1];   // weight [4, 512]
    float* out = (float*)d_out;               // [idx(2T), weight(2T), loss(1)]

    moe_gate_kernel<<<NBLK, 256>>>(x, w, out);
}